// round 11
// baseline (speedup 1.0000x reference)
#include <cuda_runtime.h>
#include <cuda_bf16.h>

#define NN 1000000
#define NE 16000000

// -------- scratch (device globals; no allocation allowed) --------
__device__ float2 g_aggc[NN];    // {sum of x[src], count}
__device__ float4 g_h1[NN];
__device__ float4 g_sum2[NN];
__device__ float4 g_h2[NN];
__device__ float2 g_p3[NN];      // h2 @ W3l (projected to dim 2 before scatter)
__device__ float2 g_sum3[NN];    // accumulated projected values
__device__ float  g_inv[NN];     // 1 / max(count, 1)

__device__ __forceinline__ void red_add_v2(float2* addr, float a, float b) {
    asm volatile("red.global.add.v2.f32 [%0], {%1, %2};"
                 :: "l"(addr), "f"(a), "f"(b) : "memory");
}
__device__ __forceinline__ void red_add_v4(float4* addr, float4 v) {
    asm volatile("red.global.add.v4.f32 [%0], {%1, %2, %3, %4};"
                 :: "l"(addr), "f"(v.x), "f"(v.y), "f"(v.z), "f"(v.w) : "memory");
}
// streaming (evict-first) load for the one-shot edge index stream
__device__ __forceinline__ int4 ldcs_int4(const int4* p) {
    int4 v;
    asm volatile("ld.global.cs.v4.s32 {%0,%1,%2,%3}, [%4];"
                 : "=r"(v.x), "=r"(v.y), "=r"(v.z), "=r"(v.w) : "l"(p));
    return v;
}
// L2 evict-last cache policy (valid for any width via cache_hint form)
__device__ __forceinline__ unsigned long long mk_evict_last_policy() {
    unsigned long long pol;
    asm("createpolicy.fractional.L2::evict_last.b64 %0, 1.0;" : "=l"(pol));
    return pol;
}
__device__ __forceinline__ float ldel_f(const float* p, unsigned long long pol) {
    float v;
    asm volatile("ld.global.L2::cache_hint.f32 %0, [%1], %2;"
                 : "=f"(v) : "l"(p), "l"(pol));
    return v;
}
__device__ __forceinline__ float2 ldel_f2(const float2* p, unsigned long long pol) {
    float2 v;
    asm volatile("ld.global.L2::cache_hint.v2.f32 {%0,%1}, [%2], %3;"
                 : "=f"(v.x), "=f"(v.y) : "l"(p), "l"(pol));
    return v;
}
__device__ __forceinline__ float4 ldel_f4(const float4* p, unsigned long long pol) {
    float4 v;
    asm volatile("ld.global.L2::cache_hint.v4.f32 {%0,%1,%2,%3}, [%4], %5;"
                 : "=f"(v.x), "=f"(v.y), "=f"(v.z), "=f"(v.w) : "l"(p), "l"(pol));
    return v;
}

// -------- zero aggc only (immediately before edge1's scatter: warms L2) --------
__global__ void k_zero() {
    int i = blockIdx.x * blockDim.x + threadIdx.x;
    if (i < NN / 2) ((float4*)g_aggc)[i] = make_float4(0.f, 0.f, 0.f, 0.f);
}

// -------- pass 1: scatter {x[src], 1} to aggc[dst], 4 edges/thread --------
__global__ void k_edge1(const int4* __restrict__ src4,
                        const int4* __restrict__ dst4,
                        const float* __restrict__ x) {
    int t = blockIdx.x * blockDim.x + threadIdx.x;
    if (t >= NE / 4) return;
    unsigned long long pol = mk_evict_last_policy();
    int4 s = ldcs_int4(&src4[t]);
    int4 d = ldcs_int4(&dst4[t]);
    float x0 = ldel_f(&x[s.x], pol);
    float x1 = ldel_f(&x[s.y], pol);
    float x2 = ldel_f(&x[s.z], pol);
    float x3 = ldel_f(&x[s.w], pol);
    red_add_v2(&g_aggc[d.x], x0, 1.0f);
    red_add_v2(&g_aggc[d.y], x1, 1.0f);
    red_add_v2(&g_aggc[d.z], x2, 1.0f);
    red_add_v2(&g_aggc[d.w], x3, 1.0f);
}

// -------- node 1: 2 nodes/thread; h1 = relu(mean1*W1l + b1 + x*W1r); zero sum2 --------
__global__ void k_node1(const float* __restrict__ x,
                        const float* __restrict__ W1l, const float* __restrict__ b1,
                        const float* __restrict__ W1r) {
    int t = blockIdx.x * blockDim.x + threadIdx.x;
    if (t >= NN / 2) return;
    float4 ac = ((const float4*)g_aggc)[t];          // 2 nodes: {s0,c0,s1,c1}
    float2 xv = ((const float2*)x)[t];

    float wl0 = W1l[0], wl1 = W1l[1], wl2 = W1l[2], wl3 = W1l[3];
    float bb0 = b1[0],  bb1 = b1[1],  bb2 = b1[2],  bb3 = b1[3];
    float wr0 = W1r[0], wr1 = W1r[1], wr2 = W1r[2], wr3 = W1r[3];

    float inv0 = 1.0f / fmaxf(ac.y, 1.0f);
    float inv1 = 1.0f / fmaxf(ac.w, 1.0f);
    ((float2*)g_inv)[t] = make_float2(inv0, inv1);

    float m0 = ac.x * inv0, m1 = ac.z * inv1;
    float4 h0, h1v;
    h0.x  = fmaxf(m0 * wl0 + bb0 + xv.x * wr0, 0.f);
    h0.y  = fmaxf(m0 * wl1 + bb1 + xv.x * wr1, 0.f);
    h0.z  = fmaxf(m0 * wl2 + bb2 + xv.x * wr2, 0.f);
    h0.w  = fmaxf(m0 * wl3 + bb3 + xv.x * wr3, 0.f);
    h1v.x = fmaxf(m1 * wl0 + bb0 + xv.y * wr0, 0.f);
    h1v.y = fmaxf(m1 * wl1 + bb1 + xv.y * wr1, 0.f);
    h1v.z = fmaxf(m1 * wl2 + bb2 + xv.y * wr2, 0.f);
    h1v.w = fmaxf(m1 * wl3 + bb3 + xv.y * wr3, 0.f);
    g_h1[2 * t]     = h0;
    g_h1[2 * t + 1] = h1v;
    float4 z = make_float4(0.f, 0.f, 0.f, 0.f);
    g_sum2[2 * t]     = z;     // warm sum2 for edge2
    g_sum2[2 * t + 1] = z;
}

// -------- pass 2: sum2[dst] += h1[src], 4 edges/thread --------
__global__ void k_edge2(const int4* __restrict__ src4,
                        const int4* __restrict__ dst4) {
    int t = blockIdx.x * blockDim.x + threadIdx.x;
    if (t >= NE / 4) return;
    unsigned long long pol = mk_evict_last_policy();
    int4 s = ldcs_int4(&src4[t]);
    int4 d = ldcs_int4(&dst4[t]);
    float4 v0 = ldel_f4(&g_h1[s.x], pol);
    float4 v1 = ldel_f4(&g_h1[s.y], pol);
    float4 v2 = ldel_f4(&g_h1[s.z], pol);
    float4 v3 = ldel_f4(&g_h1[s.w], pol);
    red_add_v4(&g_sum2[d.x], v0);
    red_add_v4(&g_sum2[d.y], v1);
    red_add_v4(&g_sum2[d.z], v2);
    red_add_v4(&g_sum2[d.w], v3);
}

// -------- node 2: 2 nodes/thread; h2 = relu(...); p3 = h2@W3l; zero sum3 --------
__global__ void k_node2(const float* __restrict__ W2l, const float* __restrict__ b2,
                        const float* __restrict__ W2r, const float* __restrict__ W3l) {
    int t = blockIdx.x * blockDim.x + threadIdx.x;
    if (t >= NN / 2) return;
    float2 invv = ((const float2*)g_inv)[t];

    float wl[16], wr[16], bb[4], w3[8];
    #pragma unroll
    for (int j = 0; j < 16; j++) { wl[j] = W2l[j]; wr[j] = W2r[j]; }
    #pragma unroll
    for (int j = 0; j < 4; j++) bb[j] = b2[j];
    #pragma unroll
    for (int j = 0; j < 8; j++) w3[j] = W3l[j];

    float2 p3loc[2];
    #pragma unroll
    for (int k = 0; k < 2; k++) {
        int i = 2 * t + k;
        float inv = (k == 0) ? invv.x : invv.y;
        float4 s = g_sum2[i];
        float4 m = make_float4(s.x * inv, s.y * inv, s.z * inv, s.w * inv);
        float4 p = g_h1[i];
        float4 h;
        #pragma unroll
        for (int j = 0; j < 4; j++) {
            float v = bb[j];
            v += m.x * wl[0 * 4 + j] + m.y * wl[1 * 4 + j]
               + m.z * wl[2 * 4 + j] + m.w * wl[3 * 4 + j];
            v += p.x * wr[0 * 4 + j] + p.y * wr[1 * 4 + j]
               + p.z * wr[2 * 4 + j] + p.w * wr[3 * 4 + j];
            ((float*)&h)[j] = fmaxf(v, 0.f);
        }
        g_h2[i] = h;
        p3loc[k].x = h.x * w3[0] + h.y * w3[2] + h.z * w3[4] + h.w * w3[6];
        p3loc[k].y = h.x * w3[1] + h.y * w3[3] + h.z * w3[5] + h.w * w3[7];
    }
    ((float4*)g_p3)[t]   = make_float4(p3loc[0].x, p3loc[0].y, p3loc[1].x, p3loc[1].y);
    ((float4*)g_sum3)[t] = make_float4(0.f, 0.f, 0.f, 0.f);  // warm sum3 for edge3
}

// -------- pass 3: sum3[dst] += p3[src] (dim 2), 4 edges/thread --------
__global__ void k_edge3(const int4* __restrict__ src4,
                        const int4* __restrict__ dst4) {
    int t = blockIdx.x * blockDim.x + threadIdx.x;
    if (t >= NE / 4) return;
    unsigned long long pol = mk_evict_last_policy();
    int4 s = ldcs_int4(&src4[t]);
    int4 d = ldcs_int4(&dst4[t]);
    float2 v0 = ldel_f2(&g_p3[s.x], pol);
    float2 v1 = ldel_f2(&g_p3[s.y], pol);
    float2 v2 = ldel_f2(&g_p3[s.z], pol);
    float2 v3 = ldel_f2(&g_p3[s.w], pol);
    red_add_v2(&g_sum3[d.x], v0.x, v0.y);
    red_add_v2(&g_sum3[d.y], v1.x, v1.y);
    red_add_v2(&g_sum3[d.z], v2.x, v2.y);
    red_add_v2(&g_sum3[d.w], v3.x, v3.y);
}

// -------- node 3: 2 nodes/thread; h3 = relu(...); out = h3@Wc + bc --------
__global__ void k_node3(const float* __restrict__ b3,
                        const float* __restrict__ W3r,
                        const float* __restrict__ Wc, const float* __restrict__ bc,
                        float* __restrict__ out) {
    int t = blockIdx.x * blockDim.x + threadIdx.x;
    if (t >= NN / 2) return;
    float2 invv = ((const float2*)g_inv)[t];
    float4 sv = ((const float4*)g_sum3)[t];   // 2 nodes of projected sums

    float wr[8], b3l0 = b3[0], b3l1 = b3[1], wc0 = Wc[0], wc1 = Wc[1], wc2 = Wc[2], wc3 = Wc[3];
    float bc0 = bc[0], bc1 = bc[1];
    #pragma unroll
    for (int j = 0; j < 8; j++) wr[j] = W3r[j];

    float2 hloc[2], oloc[2];
    #pragma unroll
    for (int k = 0; k < 2; k++) {
        int i = 2 * t + k;
        float inv = (k == 0) ? invv.x : invv.y;
        float sx  = (k == 0) ? sv.x : sv.z;
        float sy  = (k == 0) ? sv.y : sv.w;
        float4 p = g_h2[i];
        float h0 = b3l0 + sx * inv + p.x * wr[0] + p.y * wr[2] + p.z * wr[4] + p.w * wr[6];
        float h1 = b3l1 + sy * inv + p.x * wr[1] + p.y * wr[3] + p.z * wr[5] + p.w * wr[7];
        h0 = fmaxf(h0, 0.f);
        h1 = fmaxf(h1, 0.f);
        hloc[k] = make_float2(h0, h1);
        oloc[k] = make_float2(h0 * wc0 + h1 * wc2 + bc0,
                              h0 * wc1 + h1 * wc3 + bc1);
    }
    // output layout: (out [NN,2], h3 [NN,2]) flattened in order
    float4* out4 = (float4*)out;
    out4[t]          = make_float4(oloc[0].x, oloc[0].y, oloc[1].x, oloc[1].y);
    out4[NN / 2 + t] = make_float4(hloc[0].x, hloc[0].y, hloc[1].x, hloc[1].y);
}

extern "C" void kernel_launch(void* const* d_in, const int* in_sizes, int n_in,
                              void* d_out, int out_size) {
    const float* x   = (const float*)d_in[0];
    const int*   ei  = (const int*)d_in[1];   // int64 in reference -> delivered as int32 [2, E]
    const int4*  src4 = (const int4*)ei;
    const int4*  dst4 = (const int4*)(ei + NE);
    const float* W1l = (const float*)d_in[2];
    const float* b1  = (const float*)d_in[3];
    const float* W1r = (const float*)d_in[4];
    const float* W2l = (const float*)d_in[5];
    const float* b2  = (const float*)d_in[6];
    const float* W2r = (const float*)d_in[7];
    const float* W3l = (const float*)d_in[8];
    const float* b3  = (const float*)d_in[9];
    const float* W3r = (const float*)d_in[10];
    const float* Wc  = (const float*)d_in[11];
    const float* bc  = (const float*)d_in[12];
    float* out = (float*)d_out;

    const int BT = 256;
    const int gridN2 = (NN / 2 + BT - 1) / BT;
    const int gridE4 = (NE / 4 + BT - 1) / BT;

    k_zero<<<gridN2, BT>>>();
    k_edge1<<<gridE4, BT>>>(src4, dst4, x);
    k_node1<<<gridN2, BT>>>(x, W1l, b1, W1r);
    k_edge2<<<gridE4, BT>>>(src4, dst4);
    k_node2<<<gridN2, BT>>>(W2l, b2, W2r, W3l);
    k_edge3<<<gridE4, BT>>>(src4, dst4);
    k_node3<<<gridN2, BT>>>(b3, W3r, Wc, bc, out);
}